// round 4
// baseline (speedup 1.0000x reference)
#include <cuda_runtime.h>

// Scratch: q/kv projections (fp32). Pixel linear order: ((b*64+P)*64+R)*16 + (i*4+j)
__device__ __align__(16) float g_q [2u*64*64*16*256];  // 134 MB
__device__ __align__(16) float g_kv[2u*64*64*16*512];  // 268 MB

__device__ __forceinline__ float ex2f(float x) {
    float y; asm("ex2.approx.ftz.f32 %0, %1;" : "=f"(y) : "f"(x)); return y;
}
__device__ __forceinline__ unsigned su32(const void* p) {
    return (unsigned)__cvta_generic_to_shared(p);
}
__device__ __forceinline__ void stage_tile(float* dst, const float4* src, int tid) {
    #pragma unroll
    for (int ii = 0; ii < 16; ii++) {
        int i4 = ii * 128 + tid;                 // pixel = ii, c4 = tid (conflict-free)
        asm volatile("cp.async.ca.shared.global [%0], [%1], 16;"
                     :: "r"(su32(dst + i4 * 4)), "l"(src + i4) : "memory");
    }
    asm volatile("cp.async.commit_group;" ::: "memory");
}

// ---------------------------------------------------------------------------
// Pass 1: proj = x @ w_in.T + b_in   (M=131072 px, N=768, K=128)
// ---------------------------------------------------------------------------
__global__ void proj_kernel(const float* __restrict__ x,
                            const float* __restrict__ w_in,
                            const float* __restrict__ b_in)
{
    __shared__ float  xs[64 * 128];
    __shared__ float4 ws4[64 * 16];

    const int t   = blockIdx.x;
    const int b   = t >> 10;
    const int P   = (t >> 4) & 63;
    const int R0  = (t & 15) << 2;
    const int tid = threadIdx.x;

    const float* xb = x + b * 128 * 65536;
    #pragma unroll
    for (int ii = 0; ii < 8; ii++) {
        int idx = tid + ii * 256;
        int c  = idx >> 4;
        int rj = idx & 15;
        int Rl = rj >> 2, j = rj & 3;
        int hh = (R0 + Rl) * 4 + j;
        float4 v = *(const float4*)(xb + (c * 256 + hh) * 256 + P * 4);
        int mb_ = Rl * 16 + j;
        xs[(mb_ + 0)  * 128 + c] = v.x;
        xs[(mb_ + 4)  * 128 + c] = v.y;
        xs[(mb_ + 8)  * 128 + c] = v.z;
        xs[(mb_ + 12) * 128 + c] = v.w;
    }

    const int tn = tid & 15;
    const int tm = tid >> 4;
    const int blk = ((b * 64 + P) * 64 + R0) * 16;
    const float4* xs4 = (const float4*)xs;

    for (int nc = 0; nc < 12; nc++) {
        const int n0 = nc * 64;
        float acc[4][4];
        #pragma unroll
        for (int mm = 0; mm < 4; mm++)
            #pragma unroll
            for (int nn = 0; nn < 4; nn++) acc[mm][nn] = 0.f;

        for (int kc = 0; kc < 2; kc++) {
            __syncthreads();
            #pragma unroll
            for (int ii = 0; ii < 4; ii++) {
                int idx = tid + ii * 256;
                int n = idx >> 4, kq = idx & 15;
                float4 v = *(const float4*)(w_in + (n0 + n) * 128 + kc * 64 + kq * 4);
                ws4[n * 16 + (kq ^ (n & 15))] = v;
            }
            __syncthreads();

            #pragma unroll
            for (int k4 = 0; k4 < 16; k4++) {
                float4 a[4], bb[4];
                #pragma unroll
                for (int mm = 0; mm < 4; mm++)
                    a[mm] = xs4[(tm + 16 * mm) * 32 + kc * 16 + k4];
                #pragma unroll
                for (int nn = 0; nn < 4; nn++) {
                    int n = tn + 16 * nn;
                    bb[nn] = ws4[n * 16 + (k4 ^ (n & 15))];
                }
                #pragma unroll
                for (int mm = 0; mm < 4; mm++)
                    #pragma unroll
                    for (int nn = 0; nn < 4; nn++) {
                        acc[mm][nn] += a[mm].x * bb[nn].x;
                        acc[mm][nn] += a[mm].y * bb[nn].y;
                        acc[mm][nn] += a[mm].z * bb[nn].z;
                        acc[mm][nn] += a[mm].w * bb[nn].w;
                    }
            }
        }

        #pragma unroll
        for (int nn = 0; nn < 4; nn++) {
            int n = n0 + tn + 16 * nn;
            float bi = __ldg(b_in + n);
            #pragma unroll
            for (int mm = 0; mm < 4; mm++) {
                int m = tm + 16 * mm;
                float v = acc[mm][nn] + bi;
                if (n < 256) g_q [(size_t)(blk + m) * 256 + n]         = v;
                else         g_kv[(size_t)(blk + m) * 512 + (n - 256)] = v;
            }
        }
    }
}

// ---------------------------------------------------------------------------
// Pass 2: attention, 2 query blocks per CTA (R0, R0+1), 2 queries per thread.
// 128 threads: tid = blk*64 + h*8 + qp  (queries 2qp, 2qp+1).
// Dynamic smem pool (18432 floats): [bufA 8192][bufB 8192][pce 2048]
// epilogue reuse:                    [obuf 32x260 = 8320][wbuf 64x132 at +8320]
// ---------------------------------------------------------------------------
__global__ __launch_bounds__(128) void attn_kernel(
    const float* __restrict__ w_out, const float* __restrict__ b_out,
    const float* __restrict__ pce,   float* __restrict__ out)
{
    extern __shared__ float pool[];
    float* pcesm = pool + 16384;

    const int bx  = blockIdx.x;
    const int b   = bx >> 11;
    const int P   = (bx >> 5) & 63;
    const int R0  = (bx & 31) << 1;
    const int tid = threadIdx.x;
    const int blk = tid >> 6;
    const int h   = (tid >> 3) & 7;
    const int qp  = tid & 7;
    const int q0  = qp * 2;
    const int iq  = q0 >> 2, jq = q0 & 3;

    const float LOG2E = 1.4426950408889634f;
    for (int i = tid; i < 2048; i += 128) pcesm[i] = pce[i] * LOG2E;

    // queries in registers, pre-scaled by (1/sqrt(DH)) * log2(e)
    const float SC = 0.17677669529663687f * LOG2E;
    float qa[32], qb[32];
    {
        const float* qbase = g_q + ((size_t)((b * 64 + P) * 64 + (R0 + blk)) * 16) * 256 + h * 32;
        const float4* p0 = (const float4*)(qbase + q0 * 256);
        const float4* p1 = (const float4*)(qbase + (q0 + 1) * 256);
        #pragma unroll
        for (int d4 = 0; d4 < 8; d4++) {
            float4 v = p0[d4];
            qa[d4*4+0] = v.x * SC; qa[d4*4+1] = v.y * SC;
            qa[d4*4+2] = v.z * SC; qa[d4*4+3] = v.w * SC;
            float4 w = p1[d4];
            qb[d4*4+0] = w.x * SC; qb[d4*4+1] = w.y * SC;
            qb[d4*4+2] = w.z * SC; qb[d4*4+3] = w.w * SC;
        }
    }

    float acc0[32], acc1[32];
    #pragma unroll
    for (int d = 0; d < 32; d++) { acc0[d] = 0.f; acc1[d] = 0.f; }
    float m0 = -1e30f, m1 = -1e30f, l0 = 0.f, l1 = 0.f;

    // valid kv tile list: rows R0-1..R0+2, cols P-1..P+1
    int tP[12], tR[12], tC[12];
    int nt = 0;
    for (int rr = 0; rr < 4; rr++) {
        int Rp = R0 - 1 + rr;
        if (Rp < 0 || Rp > 63) continue;
        for (int cc = 0; cc < 3; cc++) {
            int Pp = P - 1 + cc;
            if (Pp < 0 || Pp > 63) continue;
            tP[nt] = Pp; tR[nt] = Rp; tC[nt] = rr * 4 + cc; nt++;
        }
    }

    stage_tile(pool, (const float4*)(g_kv + (size_t)((b * 64 + tP[0]) * 64 + tR[0]) * 16 * 512), tid);

    for (int t = 0; t < nt; t++) {
        if (t + 1 < nt) {
            stage_tile(pool + ((t + 1) & 1) * 8192,
                       (const float4*)(g_kv + (size_t)((b * 64 + tP[t+1]) * 64 + tR[t+1]) * 16 * 512), tid);
            asm volatile("cp.async.wait_group 1;" ::: "memory");
        } else {
            asm volatile("cp.async.wait_group 0;" ::: "memory");
        }
        __syncthreads();

        const int rr = tC[t] >> 2, cc = tC[t] & 3;
        const bool act = blk ? (rr >= 1) : (rr <= 2);
        if (act) {
            const float* buf = pool + (t & 1) * 8192;
            const int dr = rr - blk, dp = cc;

            float s0[16], s1[16];
            #pragma unroll
            for (int kp = 0; kp < 16; kp++) {
                const float* kr = buf + kp * 512 + h * 32;
                float a0 = 0.f, b0_ = 0.f, a1 = 0.f, b1_ = 0.f;
                #pragma unroll
                for (int dd = 0; dd < 8; dd++) {
                    int e = (dd + h) & 7;            // head-rotated: conflict-free
                    float4 kk = *(const float4*)(kr + e * 4);
                    a0  += qa[e*4+0] * kk.x + qa[e*4+2] * kk.z;
                    b0_ += qa[e*4+1] * kk.y + qa[e*4+3] * kk.w;
                    a1  += qb[e*4+0] * kk.x + qb[e*4+2] * kk.z;
                    b1_ += qb[e*4+1] * kk.y + qb[e*4+3] * kk.w;
                }
                int ik = kp >> 2, jk = kp & 3;
                int nu  = dp * 4 + ik + 4 - iq;
                int ntt = dr * 4 + jk + 4 - jq;
                s0[kp] = (a0 + b0_) - pcesm[h * 256 + nu * 16 + ntt];
                s1[kp] = (a1 + b1_) - pcesm[h * 256 + nu * 16 + ntt - 1];
            }

            float mb0 = s0[0], mb1 = s1[0];
            #pragma unroll
            for (int kp = 1; kp < 16; kp++) { mb0 = fmaxf(mb0, s0[kp]); mb1 = fmaxf(mb1, s1[kp]); }
            float nm0 = fmaxf(m0, mb0), nm1 = fmaxf(m1, mb1);
            float f0 = ex2f(m0 - nm0), f1 = ex2f(m1 - nm1);
            m0 = nm0; m1 = nm1;
            l0 *= f0;  l1 *= f1;
            #pragma unroll
            for (int d = 0; d < 32; d++) { acc0[d] *= f0; acc1[d] *= f1; }

            float sp0 = 0.f, sp1 = 0.f;
            #pragma unroll
            for (int kp = 0; kp < 16; kp++) {
                float p0 = ex2f(s0[kp] - m0);
                float p1 = ex2f(s1[kp] - m1);
                sp0 += p0; sp1 += p1;
                const float* vr = buf + kp * 512 + 256 + h * 32;
                #pragma unroll
                for (int dd = 0; dd < 8; dd++) {
                    int e = (dd + h) & 7;
                    float4 vv = *(const float4*)(vr + e * 4);
                    acc0[e*4+0] += p0 * vv.x; acc0[e*4+1] += p0 * vv.y;
                    acc0[e*4+2] += p0 * vv.z; acc0[e*4+3] += p0 * vv.w;
                    acc1[e*4+0] += p1 * vv.x; acc1[e*4+1] += p1 * vv.y;
                    acc1[e*4+2] += p1 * vv.z; acc1[e*4+3] += p1 * vv.w;
                }
            }
            l0 += sp0; l1 += sp1;
        }
        __syncthreads();
    }

    // stage normalized attention output: obuf[pix][k], pix = blk*16 + q, pad 260
    float* obuf = pool;
    {
        float inv0 = 1.0f / l0, inv1 = 1.0f / l1;
        float4* r0 = (float4*)(obuf + (blk * 16 + q0)     * 260 + h * 32);
        float4* r1 = (float4*)(obuf + (blk * 16 + q0 + 1) * 260 + h * 32);
        #pragma unroll
        for (int d4 = 0; d4 < 8; d4++) {
            float4 v;
            v.x = acc0[d4*4+0] * inv0; v.y = acc0[d4*4+1] * inv0;
            v.z = acc0[d4*4+2] * inv0; v.w = acc0[d4*4+3] * inv0;
            r0[d4] = v;
            float4 w;
            w.x = acc1[d4*4+0] * inv1; w.y = acc1[d4*4+1] * inv1;
            w.z = acc1[d4*4+2] * inv1; w.w = acc1[d4*4+3] * inv1;
            r1[d4] = w;
        }
    }

    // Fused output projection: out32x128 = obuf(32x256) @ w_out.T + b_out
    // thread = (cg 16, pg 8): pg = (eb,ej); 4 w-positions x 8 channels per thread.
    float* wbuf = pool + 8320;                 // [kk 0..63][c 0..127], stride 132
    const int cg = tid >> 3, pg = tid & 7;
    const int eb = pg >> 2, ej = pg & 3;
    const int c0 = cg * 8;

    float accO[4][8];
    #pragma unroll
    for (int i = 0; i < 4; i++)
        #pragma unroll
        for (int ci = 0; ci < 8; ci++) accO[i][ci] = 0.f;

    for (int kc = 0; kc < 4; kc++) {
        __syncthreads();
        // stage w_out chunk transposed: wbuf[kk][c] = w_out[c][kc*64+kk]
        const float4* wsrc = (const float4*)w_out + tid * 64 + kc * 16;
        #pragma unroll
        for (int ii = 0; ii < 16; ii++) {
            float4 w4 = __ldg(wsrc + ii);
            wbuf[(ii*4+0) * 132 + tid] = w4.x;
            wbuf[(ii*4+1) * 132 + tid] = w4.y;
            wbuf[(ii*4+2) * 132 + tid] = w4.z;
            wbuf[(ii*4+3) * 132 + tid] = w4.w;
        }
        __syncthreads();

        #pragma unroll 4
        for (int kk4 = 0; kk4 < 16; kk4++) {
            float4 ov[4];
            #pragma unroll
            for (int i = 0; i < 4; i++)
                ov[i] = *(const float4*)(obuf + (eb * 16 + ej + 4 * i) * 260 + kc * 64 + kk4 * 4);
            #pragma unroll
            for (int s = 0; s < 4; s++) {
                float4 wa = *(const float4*)(wbuf + (kk4 * 4 + s) * 132 + c0);
                float4 wb = *(const float4*)(wbuf + (kk4 * 4 + s) * 132 + c0 + 4);
                #pragma unroll
                for (int i = 0; i < 4; i++) {
                    float o = (s == 0) ? ov[i].x : (s == 1) ? ov[i].y : (s == 2) ? ov[i].z : ov[i].w;
                    accO[i][0] += o * wa.x; accO[i][1] += o * wa.y;
                    accO[i][2] += o * wa.z; accO[i][3] += o * wa.w;
                    accO[i][4] += o * wb.x; accO[i][5] += o * wb.y;
                    accO[i][6] += o * wb.z; accO[i][7] += o * wb.w;
                }
            }
        }
    }

    const int hh = (R0 + eb) * 4 + ej;
    #pragma unroll
    for (int ci = 0; ci < 8; ci++) {
        int c = c0 + ci;
        float bo = __ldg(b_out + c);
        float4 r;
        r.x = accO[0][ci] + bo; r.y = accO[1][ci] + bo;
        r.z = accO[2][ci] + bo; r.w = accO[3][ci] + bo;
        *(float4*)(out + ((size_t)(b * 128 + c) * 256 + hh) * 256 + P * 4) = r;
    }
}

// ---------------------------------------------------------------------------
extern "C" void kernel_launch(void* const* d_in, const int* in_sizes, int n_in,
                              void* d_out, int out_size)
{
    const float* x     = (const float*)d_in[0];
    const float* w_in  = (const float*)d_in[1];
    const float* b_in  = (const float*)d_in[2];
    const float* w_out = (const float*)d_in[3];
    const float* b_out = (const float*)d_in[4];
    const float* pce   = (const float*)d_in[5];
    float* out = (float*)d_out;

    // Unconditional (no static guards): host-side attribute set, identical on
    // every call, legal during graph capture, allocates nothing.
    cudaFuncSetAttribute(attn_kernel, cudaFuncAttributeMaxDynamicSharedMemorySize, 73728);

    proj_kernel<<<2048, 256>>>(x, w_in, b_in);
    attn_kernel<<<4096, 128, 73728>>>(w_out, b_out, pce, out);
}

// round 5
// speedup vs baseline: 1.0955x; 1.0955x over previous
#include <cuda_runtime.h>

// Scratch: q/kv projections (fp32). Pixel linear order: ((b*64+P)*64+R)*16 + (i*4+j)
__device__ __align__(16) float g_q [2u*64*64*16*256];  // 134 MB
__device__ __align__(16) float g_kv[2u*64*64*16*512];  // 268 MB

__device__ __forceinline__ float ex2f(float x) {
    float y; asm("ex2.approx.ftz.f32 %0, %1;" : "=f"(y) : "f"(x)); return y;
}
__device__ __forceinline__ unsigned su32(const void* p) {
    return (unsigned)__cvta_generic_to_shared(p);
}
// Stage one 16px x 512f kv tile (32 KB) via cp.async; conflict-free.
__device__ __forceinline__ void stage_tile(float* dst, const float4* src, int tid) {
    #pragma unroll
    for (int ii = 0; ii < 16; ii++) {
        int i4 = ii * 128 + tid;
        asm volatile("cp.async.ca.shared.global [%0], [%1], 16;"
                     :: "r"(su32(dst + i4 * 4)), "l"(src + i4) : "memory");
    }
    asm volatile("cp.async.commit_group;" ::: "memory");
}

// ---------------------------------------------------------------------------
// Pass 1: proj = x @ w_in.T + b_in   (M=131072 px, N=768, K=128)  [unchanged,
// measured at the scalar-FFMA roofline ~690us]
// ---------------------------------------------------------------------------
__global__ void proj_kernel(const float* __restrict__ x,
                            const float* __restrict__ w_in,
                            const float* __restrict__ b_in)
{
    __shared__ float  xs[64 * 128];
    __shared__ float4 ws4[64 * 16];

    const int t   = blockIdx.x;
    const int b   = t >> 10;
    const int P   = (t >> 4) & 63;
    const int R0  = (t & 15) << 2;
    const int tid = threadIdx.x;

    const float* xb = x + b * 128 * 65536;
    #pragma unroll
    for (int ii = 0; ii < 8; ii++) {
        int idx = tid + ii * 256;
        int c  = idx >> 4;
        int rj = idx & 15;
        int Rl = rj >> 2, j = rj & 3;
        int hh = (R0 + Rl) * 4 + j;
        float4 v = *(const float4*)(xb + (c * 256 + hh) * 256 + P * 4);
        int mb_ = Rl * 16 + j;
        xs[(mb_ + 0)  * 128 + c] = v.x;
        xs[(mb_ + 4)  * 128 + c] = v.y;
        xs[(mb_ + 8)  * 128 + c] = v.z;
        xs[(mb_ + 12) * 128 + c] = v.w;
    }

    const int tn = tid & 15;
    const int tm = tid >> 4;
    const int blk = ((b * 64 + P) * 64 + R0) * 16;
    const float4* xs4 = (const float4*)xs;

    for (int nc = 0; nc < 12; nc++) {
        const int n0 = nc * 64;
        float acc[4][4];
        #pragma unroll
        for (int mm = 0; mm < 4; mm++)
            #pragma unroll
            for (int nn = 0; nn < 4; nn++) acc[mm][nn] = 0.f;

        for (int kc = 0; kc < 2; kc++) {
            __syncthreads();
            #pragma unroll
            for (int ii = 0; ii < 4; ii++) {
                int idx = tid + ii * 256;
                int n = idx >> 4, kq = idx & 15;
                float4 v = *(const float4*)(w_in + (n0 + n) * 128 + kc * 64 + kq * 4);
                ws4[n * 16 + (kq ^ (n & 15))] = v;
            }
            __syncthreads();

            #pragma unroll
            for (int k4 = 0; k4 < 16; k4++) {
                float4 a[4], bb[4];
                #pragma unroll
                for (int mm = 0; mm < 4; mm++)
                    a[mm] = xs4[(tm + 16 * mm) * 32 + kc * 16 + k4];
                #pragma unroll
                for (int nn = 0; nn < 4; nn++) {
                    int n = tn + 16 * nn;
                    bb[nn] = ws4[n * 16 + (k4 ^ (n & 15))];
                }
                #pragma unroll
                for (int mm = 0; mm < 4; mm++)
                    #pragma unroll
                    for (int nn = 0; nn < 4; nn++) {
                        acc[mm][nn] += a[mm].x * bb[nn].x;
                        acc[mm][nn] += a[mm].y * bb[nn].y;
                        acc[mm][nn] += a[mm].z * bb[nn].z;
                        acc[mm][nn] += a[mm].w * bb[nn].w;
                    }
            }
        }

        #pragma unroll
        for (int nn = 0; nn < 4; nn++) {
            int n = n0 + tn + 16 * nn;
            float bi = __ldg(b_in + n);
            #pragma unroll
            for (int mm = 0; mm < 4; mm++) {
                int m = tm + 16 * mm;
                float v = acc[mm][nn] + bi;
                if (n < 256) g_q [(size_t)(blk + m) * 256 + n]         = v;
                else         g_kv[(size_t)(blk + m) * 512 + (n - 256)] = v;
            }
        }
    }
}

// ---------------------------------------------------------------------------
// Pass 2: attention + fused out-projection. One CTA per (b,P,R) block.
// 128 threads: tid = h*16 + qq. 1 query per thread (reg-safe: ~140 regs).
// Dyn smem (18432 floats): [bufA 8192][bufB 8192][pce 2048]; obuf reuses bufA.
// ---------------------------------------------------------------------------
__global__ __launch_bounds__(128) void attn_kernel(
    const float* __restrict__ w_out, const float* __restrict__ b_out,
    const float* __restrict__ pce,   float* __restrict__ out)
{
    extern __shared__ float pool[];
    float* pcesm = pool + 16384;

    const int bx = blockIdx.x;
    const int b  = bx >> 12;
    const int P  = (bx >> 6) & 63;
    const int R  = bx & 63;
    const int tid = threadIdx.x;
    const int h  = tid >> 4;
    const int qq = tid & 15;
    const int iq = qq >> 2, jq = qq & 3;

    const float LOG2E = 1.4426950408889634f;
    for (int i = tid; i < 2048; i += 128) pcesm[i] = pce[i] * LOG2E;

    // q row in registers, pre-scaled by (1/sqrt(DH)) * log2(e)
    const float SC = 0.17677669529663687f * LOG2E;
    float q[32];
    {
        const float4* qp = (const float4*)(g_q + ((size_t)(((b * 64 + P) * 64 + R) * 16 + qq)) * 256 + h * 32);
        #pragma unroll
        for (int d4 = 0; d4 < 8; d4++) {
            float4 v = qp[d4];
            q[d4*4+0] = v.x * SC; q[d4*4+1] = v.y * SC;
            q[d4*4+2] = v.z * SC; q[d4*4+3] = v.w * SC;
        }
    }

    float acc[32];
    #pragma unroll
    for (int d = 0; d < 32; d++) acc[d] = 0.f;
    float mrun = -1e30f;
    float l = 0.f;

    // valid kv tile list (3x3 neighborhood; boundary skip == -inf mask)
    int tP[9], tR[9], tC[9];
    int nt = 0;
    for (int dp = 0; dp < 3; dp++) {
        int Pp = P + dp - 1;
        if (Pp < 0 || Pp > 63) continue;
        for (int dr = 0; dr < 3; dr++) {
            int Rp = R + dr - 1;
            if (Rp < 0 || Rp > 63) continue;
            tP[nt] = Pp; tR[nt] = Rp; tC[nt] = dp * 4 + dr; nt++;
        }
    }

    stage_tile(pool, (const float4*)(g_kv + (size_t)((b * 64 + tP[0]) * 64 + tR[0]) * 16 * 512), tid);

    for (int t = 0; t < nt; t++) {
        if (t + 1 < nt) {
            stage_tile(pool + ((t + 1) & 1) * 8192,
                       (const float4*)(g_kv + (size_t)((b * 64 + tP[t+1]) * 64 + tR[t+1]) * 16 * 512), tid);
            asm volatile("cp.async.wait_group 1;" ::: "memory");
        } else {
            asm volatile("cp.async.wait_group 0;" ::: "memory");
        }
        __syncthreads();   // tile t ready (and pcesm on first iteration)

        const float* buf = pool + (t & 1) * 8192;
        const int dp = tC[t] >> 2, dr = tC[t] & 3;

        float s[16];
        #pragma unroll
        for (int kp = 0; kp < 16; kp++) {
            const float* kr = buf + kp * 512 + h * 32;
            float d0 = 0.f, d1 = 0.f;
            #pragma unroll
            for (int dd = 0; dd < 8; dd++) {
                int e = (dd + h) & 7;            // head-rotated: conflict-free LDS
                float4 kk = *(const float4*)(kr + e * 4);
                d0 += q[e*4+0] * kk.x + q[e*4+2] * kk.z;
                d1 += q[e*4+1] * kk.y + q[e*4+3] * kk.w;
            }
            int ik = kp >> 2, jk = kp & 3;
            int nu = dp * 4 + ik + 4 - iq;
            int nv = dr * 4 + jk + 4 - jq;
            s[kp] = (d0 + d1) - pcesm[h * 256 + nu * 16 + nv];
        }

        float mb = s[0];
        #pragma unroll
        for (int kp = 1; kp < 16; kp++) mb = fmaxf(mb, s[kp]);
        float mn = fmaxf(mrun, mb);
        float f  = ex2f(mrun - mn);
        mrun = mn;
        l *= f;
        #pragma unroll
        for (int d = 0; d < 32; d++) acc[d] *= f;

        float sp = 0.f;
        #pragma unroll
        for (int kp = 0; kp < 16; kp++) {
            float p = ex2f(s[kp] - mn);
            sp += p;
            const float* vr = buf + kp * 512 + 256 + h * 32;
            #pragma unroll
            for (int dd = 0; dd < 8; dd++) {
                int e = (dd + h) & 7;
                float4 vv = *(const float4*)(vr + e * 4);
                acc[e*4+0] += p * vv.x; acc[e*4+1] += p * vv.y;
                acc[e*4+2] += p * vv.z; acc[e*4+3] += p * vv.w;
            }
        }
        l += sp;

        __syncthreads();   // allow next prefetch to overwrite this buffer
    }

    // stage normalized attention output: obuf[qq][h*32+d], row stride 260
    float* obuf = pool;
    {
        float inv = 1.0f / l;
        float4* orow = (float4*)(obuf + qq * 260 + h * 32);
        #pragma unroll
        for (int d4 = 0; d4 < 8; d4++) {
            float4 v;
            v.x = acc[d4*4+0] * inv; v.y = acc[d4*4+1] * inv;
            v.z = acc[d4*4+2] * inv; v.w = acc[d4*4+3] * inv;
            orow[d4] = v;
        }
    }
    __syncthreads();

    // Fused output projection: out16x128 = obuf(16x256) @ w_out.T + b_out
    const int j  = tid & 3;
    const int cg = tid >> 2;            // 0..31
    float accO[4][4];
    #pragma unroll
    for (int ci = 0; ci < 4; ci++)
        #pragma unroll
        for (int i = 0; i < 4; i++) accO[ci][i] = 0.f;

    #pragma unroll 8
    for (int k4 = 0; k4 < 64; k4++) {
        float4 o[4];
        #pragma unroll
        for (int i = 0; i < 4; i++)
            o[i] = *(const float4*)(obuf + (i * 4 + j) * 260 + k4 * 4);
        #pragma unroll
        for (int ci = 0; ci < 4; ci++) {
            float4 w4 = __ldg((const float4*)(w_out + (cg * 4 + ci) * 256 + k4 * 4));
            #pragma unroll
            for (int i = 0; i < 4; i++)
                accO[ci][i] += w4.x * o[i].x + w4.y * o[i].y
                             + w4.z * o[i].z + w4.w * o[i].w;
        }
    }

    #pragma unroll
    for (int ci = 0; ci < 4; ci++) {
        int c = cg * 4 + ci;
        float bo = __ldg(b_out + c);
        float4 r;
        r.x = accO[ci][0] + bo; r.y = accO[ci][1] + bo;
        r.z = accO[ci][2] + bo; r.w = accO[ci][3] + bo;
        *(float4*)(out + ((size_t)(b * 128 + c) * 256 + (R * 4 + j)) * 256 + P * 4) = r;
    }
}

// ---------------------------------------------------------------------------
extern "C" void kernel_launch(void* const* d_in, const int* in_sizes, int n_in,
                              void* d_out, int out_size)
{
    const float* x     = (const float*)d_in[0];
    const float* w_in  = (const float*)d_in[1];
    const float* b_in  = (const float*)d_in[2];
    const float* w_out = (const float*)d_in[3];
    const float* b_out = (const float*)d_in[4];
    const float* pce   = (const float*)d_in[5];
    float* out = (float*)d_out;

    // Unconditional on every call (no static guards); host-side, capture-legal.
    cudaFuncSetAttribute(attn_kernel, cudaFuncAttributeMaxDynamicSharedMemorySize, 73728);

    proj_kernel<<<2048, 256>>>(x, w_in, b_in);
    attn_kernel<<<8192, 128, 73728>>>(w_out, b_out, pce, out);
}

// round 6
// speedup vs baseline: 1.1202x; 1.0225x over previous
#include <cuda_runtime.h>

// Scratch: q/kv projections (fp32). Pixel linear order: ((b*64+P)*64+R)*16 + (i*4+j)
__device__ __align__(16) float g_q [2u*64*64*16*256];  // 134 MB
__device__ __align__(16) float g_kv[2u*64*64*16*512];  // 268 MB

__device__ __forceinline__ float ex2f(float x) {
    float y; asm("ex2.approx.ftz.f32 %0, %1;" : "=f"(y) : "f"(x)); return y;
}

// ---------------------------------------------------------------------------
// Pass 1: proj = x @ w_in.T + b_in   (M=131072 px, N=768, K=128)  [unchanged]
// ---------------------------------------------------------------------------
__global__ void proj_kernel(const float* __restrict__ x,
                            const float* __restrict__ w_in,
                            const float* __restrict__ b_in)
{
    __shared__ float  xs[64 * 128];
    __shared__ float4 ws4[64 * 16];

    const int t   = blockIdx.x;
    const int b   = t >> 10;
    const int P   = (t >> 4) & 63;
    const int R0  = (t & 15) << 2;
    const int tid = threadIdx.x;

    const float* xb = x + b * 128 * 65536;
    #pragma unroll
    for (int ii = 0; ii < 8; ii++) {
        int idx = tid + ii * 256;
        int c  = idx >> 4;
        int rj = idx & 15;
        int Rl = rj >> 2, j = rj & 3;
        int hh = (R0 + Rl) * 4 + j;
        float4 v = *(const float4*)(xb + (c * 256 + hh) * 256 + P * 4);
        int mb_ = Rl * 16 + j;
        xs[(mb_ + 0)  * 128 + c] = v.x;
        xs[(mb_ + 4)  * 128 + c] = v.y;
        xs[(mb_ + 8)  * 128 + c] = v.z;
        xs[(mb_ + 12) * 128 + c] = v.w;
    }

    const int tn = tid & 15;
    const int tm = tid >> 4;
    const int blk = ((b * 64 + P) * 64 + R0) * 16;
    const float4* xs4 = (const float4*)xs;

    for (int nc = 0; nc < 12; nc++) {
        const int n0 = nc * 64;
        float acc[4][4];
        #pragma unroll
        for (int mm = 0; mm < 4; mm++)
            #pragma unroll
            for (int nn = 0; nn < 4; nn++) acc[mm][nn] = 0.f;

        for (int kc = 0; kc < 2; kc++) {
            __syncthreads();
            #pragma unroll
            for (int ii = 0; ii < 4; ii++) {
                int idx = tid + ii * 256;
                int n = idx >> 4, kq = idx & 15;
                float4 v = *(const float4*)(w_in + (n0 + n) * 128 + kc * 64 + kq * 4);
                ws4[n * 16 + (kq ^ (n & 15))] = v;
            }
            __syncthreads();

            #pragma unroll
            for (int k4 = 0; k4 < 16; k4++) {
                float4 a[4], bb[4];
                #pragma unroll
                for (int mm = 0; mm < 4; mm++)
                    a[mm] = xs4[(tm + 16 * mm) * 32 + kc * 16 + k4];
                #pragma unroll
                for (int nn = 0; nn < 4; nn++) {
                    int n = tn + 16 * nn;
                    bb[nn] = ws4[n * 16 + (k4 ^ (n & 15))];
                }
                #pragma unroll
                for (int mm = 0; mm < 4; mm++)
                    #pragma unroll
                    for (int nn = 0; nn < 4; nn++) {
                        acc[mm][nn] += a[mm].x * bb[nn].x;
                        acc[mm][nn] += a[mm].y * bb[nn].y;
                        acc[mm][nn] += a[mm].z * bb[nn].z;
                        acc[mm][nn] += a[mm].w * bb[nn].w;
                    }
            }
        }

        #pragma unroll
        for (int nn = 0; nn < 4; nn++) {
            int n = n0 + tn + 16 * nn;
            float bi = __ldg(b_in + n);
            #pragma unroll
            for (int mm = 0; mm < 4; mm++) {
                int m = tm + 16 * mm;
                float v = acc[mm][nn] + bi;
                if (n < 256) g_q [(size_t)(blk + m) * 256 + n]         = v;
                else         g_kv[(size_t)(blk + m) * 512 + (n - 256)] = v;
            }
        }
    }
}

// ---------------------------------------------------------------------------
// Pass 2: attention over 3x3 neighbor blocks + fused output projection.
// EXACT R2 structure (static smem, synchronous staging); ONLY change:
// head-rotated k/v reads (e = (dd+h)&7) for conflict-free LDS.
// One CTA per (b,P,R) block. 128 threads: thread = (head h, query qq).
// ---------------------------------------------------------------------------
__global__ __launch_bounds__(128) void attn_kernel(
    const float* __restrict__ w_out, const float* __restrict__ b_out,
    const float* __restrict__ pce,   float* __restrict__ out)
{
    __shared__ float pool[16 * 256 * 2 + 2048];   // kbuf | vbuf | pcesm (obuf reuses k/v)
    float* kbuf  = pool;
    float* vbuf  = pool + 4096;
    float* pcesm = pool + 8192;

    const int bx = blockIdx.x;
    const int b  = bx >> 12;
    const int P  = (bx >> 6) & 63;
    const int R  = bx & 63;
    const int tid = threadIdx.x;
    const int h  = tid >> 4;
    const int qq = tid & 15;
    const int iq = qq >> 2, jq = qq & 3;

    const float LOG2E = 1.4426950408889634f;
    for (int i = tid; i < 2048; i += 128) pcesm[i] = pce[i] * LOG2E;

    // q row in registers, pre-scaled by (1/sqrt(DH)) * log2(e)
    const float SC = 0.17677669529663687f * LOG2E;
    float q[32];
    {
        const float4* qp = (const float4*)(g_q + ((size_t)(((b * 64 + P) * 64 + R) * 16 + qq)) * 256 + h * 32);
        #pragma unroll
        for (int d4 = 0; d4 < 8; d4++) {
            float4 v = qp[d4];
            q[d4*4+0] = v.x * SC; q[d4*4+1] = v.y * SC;
            q[d4*4+2] = v.z * SC; q[d4*4+3] = v.w * SC;
        }
    }

    float acc[32];
    #pragma unroll
    for (int d = 0; d < 32; d++) acc[d] = 0.f;
    float mrun = -1e30f;
    float l = 0.f;

    __syncthreads();   // pcesm ready

    for (int dp = 0; dp < 3; dp++) {
        int Pp = P + dp - 1;
        if (Pp < 0 || Pp > 63) continue;
        for (int dr = 0; dr < 3; dr++) {
            int Rp = R + dr - 1;
            if (Rp < 0 || Rp > 63) continue;   // boundary skip == -inf mask

            __syncthreads();  // previous tile fully consumed
            const float4* src = (const float4*)(g_kv + (size_t)(((b * 64 + Pp) * 64 + Rp) * 16) * 512);
            float4* kb4 = (float4*)kbuf;
            float4* vb4 = (float4*)vbuf;
            #pragma unroll
            for (int ii = 0; ii < 16; ii++) {
                int idx = tid + ii * 128;      // 0..2047
                int pix = idx >> 7;
                int c4  = idx & 127;
                float4 v = src[idx];
                if (c4 < 64) kb4[pix * 64 + c4]        = v;
                else         vb4[pix * 64 + (c4 - 64)] = v;
            }
            __syncthreads();

            float s[16];
            #pragma unroll
            for (int kp = 0; kp < 16; kp++) {
                const float* kr = kbuf + kp * 256 + h * 32;
                float d0 = 0.f, d1 = 0.f;
                #pragma unroll
                for (int dd = 0; dd < 8; dd++) {
                    int e = (dd + h) & 7;            // head-rotated: conflict-free LDS
                    float4 kk = *(const float4*)(kr + e * 4);
                    d0 += q[e*4+0] * kk.x + q[e*4+2] * kk.z;
                    d1 += q[e*4+1] * kk.y + q[e*4+3] * kk.w;
                }
                int ik = kp >> 2, jk = kp & 3;
                int nu = dp * 4 + ik + 4 - iq;
                int nt = dr * 4 + jk + 4 - jq;
                s[kp] = (d0 + d1) - pcesm[h * 256 + nu * 16 + nt];
            }

            float mb = s[0];
            #pragma unroll
            for (int kp = 1; kp < 16; kp++) mb = fmaxf(mb, s[kp]);
            float mn = fmaxf(mrun, mb);
            float f  = ex2f(mrun - mn);
            mrun = mn;
            l *= f;
            #pragma unroll
            for (int d = 0; d < 32; d++) acc[d] *= f;

            float sp = 0.f;
            #pragma unroll
            for (int kp = 0; kp < 16; kp++) {
                float p = ex2f(s[kp] - mn);
                sp += p;
                const float* vr = vbuf + kp * 256 + h * 32;
                #pragma unroll
                for (int dd = 0; dd < 8; dd++) {
                    int e = (dd + h) & 7;            // head-rotated
                    float4 vv = *(const float4*)(vr + e * 4);
                    acc[e*4+0] += p * vv.x; acc[e*4+1] += p * vv.y;
                    acc[e*4+2] += p * vv.z; acc[e*4+3] += p * vv.w;
                }
            }
            l += sp;
        }
    }

    // Normalize and stage attention output: obuf[qq][h*32+d], row stride 260
    __syncthreads();                    // all kv reads done; obuf aliases kbuf/vbuf
    float* obuf = pool;
    {
        float inv = 1.0f / l;
        float4* orow = (float4*)(obuf + qq * 260 + h * 32);
        #pragma unroll
        for (int d4 = 0; d4 < 8; d4++) {
            float4 v;
            v.x = acc[d4*4+0] * inv; v.y = acc[d4*4+1] * inv;
            v.z = acc[d4*4+2] * inv; v.w = acc[d4*4+3] * inv;
            orow[d4] = v;
        }
    }
    __syncthreads();

    // Fused output projection: out16x128 = obuf(16x256) @ w_out.T + b_out
    const int j  = tid & 3;
    const int cg = tid >> 2;            // 0..31
    float accO[4][4];
    #pragma unroll
    for (int ci = 0; ci < 4; ci++)
        #pragma unroll
        for (int i = 0; i < 4; i++) accO[ci][i] = 0.f;

    #pragma unroll 8
    for (int k4 = 0; k4 < 64; k4++) {
        float4 o[4];
        #pragma unroll
        for (int i = 0; i < 4; i++)
            o[i] = *(const float4*)(obuf + (i * 4 + j) * 260 + k4 * 4);
        #pragma unroll
        for (int ci = 0; ci < 4; ci++) {
            float4 w4 = __ldg((const float4*)(w_out + (cg * 4 + ci) * 256 + k4 * 4));
            #pragma unroll
            for (int i = 0; i < 4; i++)
                accO[ci][i] += w4.x * o[i].x + w4.y * o[i].y
                             + w4.z * o[i].z + w4.w * o[i].w;
        }
    }

    #pragma unroll
    for (int ci = 0; ci < 4; ci++) {
        int c = cg * 4 + ci;
        float bo = __ldg(b_out + c);
        float4 r;
        r.x = accO[ci][0] + bo; r.y = accO[ci][1] + bo;
        r.z = accO[ci][2] + bo; r.w = accO[ci][3] + bo;
        *(float4*)(out + ((size_t)(b * 128 + c) * 256 + (R * 4 + j)) * 256 + P * 4) = r;
    }
}

// ---------------------------------------------------------------------------
extern "C" void kernel_launch(void* const* d_in, const int* in_sizes, int n_in,
                              void* d_out, int out_size)
{
    const float* x     = (const float*)d_in[0];
    const float* w_in  = (const float*)d_in[1];
    const float* b_in  = (const float*)d_in[2];
    const float* w_out = (const float*)d_in[3];
    const float* b_out = (const float*)d_in[4];
    const float* pce   = (const float*)d_in[5];
    float* out = (float*)d_out;

    proj_kernel<<<2048, 256>>>(x, w_in, b_in);
    attn_kernel<<<8192, 128>>>(w_out, b_out, pce, out);
}

// round 8
// speedup vs baseline: 3.9356x; 3.5134x over previous
#include <cuda_runtime.h>

// Scratch: q/kv projections (fp32). Pixel linear order: ((b*64+P)*64+R)*16 + (i*4+j)
__device__ __align__(16) float g_q [2u*64*64*16*256];  // 134 MB
__device__ __align__(16) float g_kv[2u*64*64*16*512];  // 268 MB

__device__ __forceinline__ float ex2f(float x) {
    float y; asm("ex2.approx.ftz.f32 %0, %1;" : "=f"(y) : "f"(x)); return y;
}

// ---------------------------------------------------------------------------
// Pass 1: proj = x @ w_in.T + b_in   (M=131072 px, N=768, K=128)  [R2-proven]
// ---------------------------------------------------------------------------
__global__ void proj_kernel(const float* __restrict__ x,
                            const float* __restrict__ w_in,
                            const float* __restrict__ b_in)
{
    __shared__ float  xs[64 * 128];
    __shared__ float4 ws4[64 * 16];

    const int t   = blockIdx.x;
    const int b   = t >> 10;
    const int P   = (t >> 4) & 63;
    const int R0  = (t & 15) << 2;
    const int tid = threadIdx.x;

    const float* xb = x + b * 128 * 65536;
    #pragma unroll
    for (int ii = 0; ii < 8; ii++) {
        int idx = tid + ii * 256;
        int c  = idx >> 4;
        int rj = idx & 15;
        int Rl = rj >> 2, j = rj & 3;
        int hh = (R0 + Rl) * 4 + j;
        float4 v = *(const float4*)(xb + (c * 256 + hh) * 256 + P * 4);
        int mb_ = Rl * 16 + j;
        xs[(mb_ + 0)  * 128 + c] = v.x;
        xs[(mb_ + 4)  * 128 + c] = v.y;
        xs[(mb_ + 8)  * 128 + c] = v.z;
        xs[(mb_ + 12) * 128 + c] = v.w;
    }

    const int tn = tid & 15;
    const int tm = tid >> 4;
    const int blk = ((b * 64 + P) * 64 + R0) * 16;
    const float4* xs4 = (const float4*)xs;

    for (int nc = 0; nc < 12; nc++) {
        const int n0 = nc * 64;
        float acc[4][4];
        #pragma unroll
        for (int mm = 0; mm < 4; mm++)
            #pragma unroll
            for (int nn = 0; nn < 4; nn++) acc[mm][nn] = 0.f;

        for (int kc = 0; kc < 2; kc++) {
            __syncthreads();
            #pragma unroll
            for (int ii = 0; ii < 4; ii++) {
                int idx = tid + ii * 256;
                int n = idx >> 4, kq = idx & 15;
                float4 v = *(const float4*)(w_in + (n0 + n) * 128 + kc * 64 + kq * 4);
                ws4[n * 16 + (kq ^ (n & 15))] = v;
            }
            __syncthreads();

            #pragma unroll
            for (int k4 = 0; k4 < 16; k4++) {
                float4 a[4], bb[4];
                #pragma unroll
                for (int mm = 0; mm < 4; mm++)
                    a[mm] = xs4[(tm + 16 * mm) * 32 + kc * 16 + k4];
                #pragma unroll
                for (int nn = 0; nn < 4; nn++) {
                    int n = tn + 16 * nn;
                    bb[nn] = ws4[n * 16 + (k4 ^ (n & 15))];
                }
                #pragma unroll
                for (int mm = 0; mm < 4; mm++)
                    #pragma unroll
                    for (int nn = 0; nn < 4; nn++) {
                        acc[mm][nn] += a[mm].x * bb[nn].x;
                        acc[mm][nn] += a[mm].y * bb[nn].y;
                        acc[mm][nn] += a[mm].z * bb[nn].z;
                        acc[mm][nn] += a[mm].w * bb[nn].w;
                    }
            }
        }

        #pragma unroll
        for (int nn = 0; nn < 4; nn++) {
            int n = n0 + tn + 16 * nn;
            float bi = __ldg(b_in + n);
            #pragma unroll
            for (int mm = 0; mm < 4; mm++) {
                int m = tm + 16 * mm;
                float v = acc[mm][nn] + bi;
                if (n < 256) g_q [(size_t)(blk + m) * 256 + n]         = v;
                else         g_kv[(size_t)(blk + m) * 512 + (n - 256)] = v;
            }
        }
    }
}

// ---------------------------------------------------------------------------
// Pass 2: attention, 2 query blocks per CTA (R0, R0+1), 2 queries per thread.
// STATIC register indexing only (no rotation). Sync LDG->STS staging (R2 style).
// 128 threads: tid = blk*64 + h*8 + qp  (queries 2qp, 2qp+1).
// Static smem pool[10240]: [kvbuf 16x512 = 8192][pce 2048]; obuf (32x260) reuses.
// ---------------------------------------------------------------------------
__global__ __launch_bounds__(128) void attn_kernel(
    const float* __restrict__ w_out, const float* __restrict__ b_out,
    const float* __restrict__ pce,   float* __restrict__ out)
{
    __shared__ float pool[10240];
    float* kvbuf = pool;
    float* pcesm = pool + 8192;

    const int bx  = blockIdx.x;
    const int b   = bx >> 11;
    const int P   = (bx >> 5) & 63;
    const int R0  = (bx & 31) << 1;
    const int tid = threadIdx.x;
    const int blk = tid >> 6;
    const int h   = (tid >> 3) & 7;
    const int qp  = tid & 7;
    const int q0  = qp * 2;
    const int iq  = q0 >> 2, jq = q0 & 3;

    const float LOG2E = 1.4426950408889634f;
    for (int i = tid; i < 2048; i += 128) pcesm[i] = pce[i] * LOG2E;

    // 2 query rows in registers, pre-scaled by (1/sqrt(DH)) * log2(e)
    const float SC = 0.17677669529663687f * LOG2E;
    float qa[32], qb[32];
    {
        const float* qbase = g_q + (size_t)(((b * 64 + P) * 64 + (R0 + blk)) * 16) * 256 + h * 32;
        const float4* p0 = (const float4*)(qbase + q0 * 256);
        const float4* p1 = (const float4*)(qbase + (q0 + 1) * 256);
        #pragma unroll
        for (int d4 = 0; d4 < 8; d4++) {
            float4 v = p0[d4];
            qa[d4*4+0] = v.x * SC; qa[d4*4+1] = v.y * SC;
            qa[d4*4+2] = v.z * SC; qa[d4*4+3] = v.w * SC;
            float4 w = p1[d4];
            qb[d4*4+0] = w.x * SC; qb[d4*4+1] = w.y * SC;
            qb[d4*4+2] = w.z * SC; qb[d4*4+3] = w.w * SC;
        }
    }

    float acc0[32], acc1[32];
    #pragma unroll
    for (int d = 0; d < 32; d++) { acc0[d] = 0.f; acc1[d] = 0.f; }
    float m0 = -1e30f, m1 = -1e30f, l0 = 0.f, l1 = 0.f;

    // kv tile list: rows R0-1..R0+2, cols P-1..P+1 (boundary skip == -inf mask)
    int tP[12], tR[12], tC[12];
    int nt = 0;
    for (int rr = 0; rr < 4; rr++) {
        int Rp = R0 - 1 + rr;
        if (Rp < 0 || Rp > 63) continue;
        for (int cc = 0; cc < 3; cc++) {
            int Pp = P - 1 + cc;
            if (Pp < 0 || Pp > 63) continue;
            tP[nt] = Pp; tR[nt] = Rp; tC[nt] = rr * 4 + cc; nt++;
        }
    }

    for (int t = 0; t < nt; t++) {
        __syncthreads();   // previous tile consumed (and pcesm on first iter)
        {
            const float4* src = (const float4*)(g_kv + (size_t)((b * 64 + tP[t]) * 64 + tR[t]) * 16 * 512);
            float4* dst = (float4*)kvbuf;
            #pragma unroll
            for (int ii = 0; ii < 16; ii++) {
                int idx = tid + ii * 128;     // pixel = idx>>7, c4 = idx&127
                dst[idx] = src[idx];
            }
        }
        __syncthreads();

        const int rr = tC[t] >> 2, cc = tC[t] & 3;
        const bool act = blk ? (rr >= 1) : (rr <= 2);
        if (act) {
            const int dr = rr - blk, dp = cc;

            float s0[16], s1[16];
            #pragma unroll
            for (int kp = 0; kp < 16; kp++) {
                const float* kr = kvbuf + kp * 512 + h * 32;
                float a0 = 0.f, c0_ = 0.f, a1 = 0.f, c1_ = 0.f;
                #pragma unroll
                for (int dd = 0; dd < 8; dd++) {      // static index: stays in RF
                    float4 kk = *(const float4*)(kr + dd * 4);
                    a0  += qa[dd*4+0] * kk.x + qa[dd*4+2] * kk.z;
                    c0_ += qa[dd*4+1] * kk.y + qa[dd*4+3] * kk.w;
                    a1  += qb[dd*4+0] * kk.x + qb[dd*4+2] * kk.z;
                    c1_ += qb[dd*4+1] * kk.y + qb[dd*4+3] * kk.w;
                }
                int ik = kp >> 2, jk = kp & 3;
                int nu  = dp * 4 + ik + 4 - iq;
                int ntt = dr * 4 + jk + 4 - jq;
                int bidx = h * 256 + nu * 16 + ntt;
                s0[kp] = (a0 + c0_) - pcesm[bidx];
                s1[kp] = (a1 + c1_) - pcesm[bidx - 1];
            }

            float mb0 = s0[0], mb1 = s1[0];
            #pragma unroll
            for (int kp = 1; kp < 16; kp++) { mb0 = fmaxf(mb0, s0[kp]); mb1 = fmaxf(mb1, s1[kp]); }
            float nm0 = fmaxf(m0, mb0), nm1 = fmaxf(m1, mb1);
            float f0 = ex2f(m0 - nm0), f1 = ex2f(m1 - nm1);
            m0 = nm0; m1 = nm1;
            l0 *= f0;  l1 *= f1;
            #pragma unroll
            for (int d = 0; d < 32; d++) { acc0[d] *= f0; acc1[d] *= f1; }

            float sp0 = 0.f, sp1 = 0.f;
            #pragma unroll
            for (int kp = 0; kp < 16; kp++) {
                float p0 = ex2f(s0[kp] - m0);
                float p1 = ex2f(s1[kp] - m1);
                sp0 += p0; sp1 += p1;
                const float* vr = kvbuf + kp * 512 + 256 + h * 32;
                #pragma unroll
                for (int dd = 0; dd < 8; dd++) {      // static index
                    float4 vv = *(const float4*)(vr + dd * 4);
                    acc0[dd*4+0] += p0 * vv.x; acc0[dd*4+1] += p0 * vv.y;
                    acc0[dd*4+2] += p0 * vv.z; acc0[dd*4+3] += p0 * vv.w;
                    acc1[dd*4+0] += p1 * vv.x; acc1[dd*4+1] += p1 * vv.y;
                    acc1[dd*4+2] += p1 * vv.z; acc1[dd*4+3] += p1 * vv.w;
                }
            }
            l0 += sp0; l1 += sp1;
        }
    }

    // Normalize + stage attention output: obuf[pix][k], pix = blk*16 + q, pad 260
    __syncthreads();                    // all kv reads done; obuf aliases kvbuf/pcesm
    float* obuf = pool;
    {
        float inv0 = 1.0f / l0, inv1 = 1.0f / l1;
        float4* r0 = (float4*)(obuf + (blk * 16 + q0)     * 260 + h * 32);
        float4* r1 = (float4*)(obuf + (blk * 16 + q0 + 1) * 260 + h * 32);
        #pragma unroll
        for (int d4 = 0; d4 < 8; d4++) {
            float4 v;
            v.x = acc0[d4*4+0] * inv0; v.y = acc0[d4*4+1] * inv0;
            v.z = acc0[d4*4+2] * inv0; v.w = acc0[d4*4+3] * inv0;
            r0[d4] = v;
            float4 w;
            w.x = acc1[d4*4+0] * inv1; w.y = acc1[d4*4+1] * inv1;
            w.z = acc1[d4*4+2] * inv1; w.w = acc1[d4*4+3] * inv1;
            r1[d4] = w;
        }
    }
    __syncthreads();

    // Fused output projection: out32x128 = obuf(32x256) @ w_out.T + b_out
    // thread = (j 4, cg 32): 4 channels x (2 blocks x 4 i-positions).
    const int j  = tid & 3;
    const int cg = tid >> 2;            // 0..31
    float accO[2][4][4];
    #pragma unroll
    for (int eb = 0; eb < 2; eb++)
        #pragma unroll
        for (int ci = 0; ci < 4; ci++)
            #pragma unroll
            for (int i = 0; i < 4; i++) accO[eb][ci][i] = 0.f;

    #pragma unroll 4
    for (int k4 = 0; k4 < 64; k4++) {
        float4 o[2][4];
        #pragma unroll
        for (int eb = 0; eb < 2; eb++)
            #pragma unroll
            for (int i = 0; i < 4; i++)
                o[eb][i] = *(const float4*)(obuf + (eb * 16 + i * 4 + j) * 260 + k4 * 4);
        #pragma unroll
        for (int ci = 0; ci < 4; ci++) {
            float4 w4 = __ldg((const float4*)(w_out + (cg * 4 + ci) * 256 + k4 * 4));
            #pragma unroll
            for (int eb = 0; eb < 2; eb++)
                #pragma unroll
                for (int i = 0; i < 4; i++)
                    accO[eb][ci][i] += w4.x * o[eb][i].x + w4.y * o[eb][i].y
                                     + w4.z * o[eb][i].z + w4.w * o[eb][i].w;
        }
    }

    #pragma unroll
    for (int eb = 0; eb < 2; eb++) {
        const int hh = (R0 + eb) * 4 + j;
        #pragma unroll
        for (int ci = 0; ci < 4; ci++) {
            int c = cg * 4 + ci;
            float bo = __ldg(b_out + c);
            float4 r;
            r.x = accO[eb][ci][0] + bo; r.y = accO[eb][ci][1] + bo;
            r.z = accO[eb][ci][2] + bo; r.w = accO[eb][ci][3] + bo;
            *(float4*)(out + ((size_t)(b * 128 + c) * 256 + hh) * 256 + P * 4) = r;
        }
    }
}

// ---------------------------------------------------------------------------
extern "C" void kernel_launch(void* const* d_in, const int* in_sizes, int n_in,
                              void* d_out, int out_size)
{
    const float* x     = (const float*)d_in[0];
    const float* w_in  = (const float*)d_in[1];
    const float* b_in  = (const float*)d_in[2];
    const float* w_out = (const float*)d_in[3];
    const float* b_out = (const float*)d_in[4];
    const float* pce   = (const float*)d_in[5];
    float* out = (float*)d_out;

    proj_kernel<<<2048, 256>>>(x, w_in, b_in);
    attn_kernel<<<4096, 128>>>(w_out, b_out, pce, out);
}

// round 10
// speedup vs baseline: 4.3237x; 1.0986x over previous
#include <cuda_runtime.h>

typedef unsigned long long ull;

// Scratch: q/kv projections (fp32). Pixel linear order: ((b*64+P)*64+R)*16 + (i*4+j)
__device__ __align__(16) float g_q [2u*64*64*16*256];  // 134 MB
__device__ __align__(16) float g_kv[2u*64*64*16*512];  // 268 MB

__device__ __forceinline__ float ex2f(float x) {
    float y; asm("ex2.approx.ftz.f32 %0, %1;" : "=f"(y) : "f"(x)); return y;
}
__device__ __forceinline__ ull pk(float lo, float hi) {
    ull r; asm("mov.b64 %0, {%1, %2};" : "=l"(r) : "f"(lo), "f"(hi)); return r;
}
__device__ __forceinline__ void upk(ull v, float& lo, float& hi) {
    asm("mov.b64 {%0, %1}, %2;" : "=f"(lo), "=f"(hi) : "l"(v));
}
__device__ __forceinline__ ull fma2(ull a, ull b, ull c) {
    ull d; asm("fma.rn.f32x2 %0, %1, %2, %3;" : "=l"(d) : "l"(a), "l"(b), "l"(c)); return d;
}
__device__ __forceinline__ ull mul2(ull a, ull b) {
    ull d; asm("mul.rn.f32x2 %0, %1, %2;" : "=l"(d) : "l"(a), "l"(b)); return d;
}
__device__ __forceinline__ float hsum2(ull v) {
    float lo, hi; upk(v, lo, hi); return lo + hi;
}

// ---------------------------------------------------------------------------
// Pass 1: proj = x @ w_in.T + b_in   (M=131072 px, N=768, K=128)
// f32x2-packed inner product (k-dim pairs; packs are free reg-pair moves).
// ---------------------------------------------------------------------------
__global__ void proj_kernel(const float* __restrict__ x,
                            const float* __restrict__ w_in,
                            const float* __restrict__ b_in)
{
    __shared__ float  xs[64 * 128];
    __shared__ float4 ws4[64 * 16];

    const int t   = blockIdx.x;
    const int b   = t >> 10;
    const int P   = (t >> 4) & 63;
    const int R0  = (t & 15) << 2;
    const int tid = threadIdx.x;

    const float* xb = x + b * 128 * 65536;
    #pragma unroll 4
    for (int ii = 0; ii < 8; ii++) {
        int idx = tid + ii * 256;
        int c  = idx >> 4;
        int rj = idx & 15;
        int Rl = rj >> 2, j = rj & 3;
        int hh = (R0 + Rl) * 4 + j;
        float4 v = *(const float4*)(xb + (c * 256 + hh) * 256 + P * 4);
        int mb_ = Rl * 16 + j;
        xs[(mb_ + 0)  * 128 + c] = v.x;
        xs[(mb_ + 4)  * 128 + c] = v.y;
        xs[(mb_ + 8)  * 128 + c] = v.z;
        xs[(mb_ + 12) * 128 + c] = v.w;
    }

    const int tn = tid & 15;
    const int tm = tid >> 4;
    const int blk = ((b * 64 + P) * 64 + R0) * 16;
    const float4* xs4 = (const float4*)xs;

    for (int nc = 0; nc < 12; nc++) {
        const int n0 = nc * 64;
        ull accp[4][4];
        #pragma unroll
        for (int mm = 0; mm < 4; mm++)
            #pragma unroll
            for (int nn = 0; nn < 4; nn++) accp[mm][nn] = 0ULL;

        for (int kc = 0; kc < 2; kc++) {
            __syncthreads();
            #pragma unroll
            for (int ii = 0; ii < 4; ii++) {
                int idx = tid + ii * 256;
                int n = idx >> 4, kq = idx & 15;
                float4 v = *(const float4*)(w_in + (n0 + n) * 128 + kc * 64 + kq * 4);
                ws4[n * 16 + (kq ^ (n & 15))] = v;
            }
            __syncthreads();

            #pragma unroll
            for (int k4 = 0; k4 < 16; k4++) {
                ull a01[4], a23[4], b01[4], b23[4];
                #pragma unroll
                for (int mm = 0; mm < 4; mm++) {
                    float4 a = xs4[(tm + 16 * mm) * 32 + kc * 16 + k4];
                    a01[mm] = pk(a.x, a.y); a23[mm] = pk(a.z, a.w);
                }
                #pragma unroll
                for (int nn = 0; nn < 4; nn++) {
                    int n = tn + 16 * nn;
                    float4 v = ws4[n * 16 + (k4 ^ (n & 15))];
                    b01[nn] = pk(v.x, v.y); b23[nn] = pk(v.z, v.w);
                }
                #pragma unroll
                for (int mm = 0; mm < 4; mm++)
                    #pragma unroll
                    for (int nn = 0; nn < 4; nn++) {
                        accp[mm][nn] = fma2(a01[mm], b01[nn], accp[mm][nn]);
                        accp[mm][nn] = fma2(a23[mm], b23[nn], accp[mm][nn]);
                    }
            }
        }

        #pragma unroll
        for (int nn = 0; nn < 4; nn++) {
            int n = n0 + tn + 16 * nn;
            float bi = __ldg(b_in + n);
            #pragma unroll
            for (int mm = 0; mm < 4; mm++) {
                int m = tm + 16 * mm;
                float v = hsum2(accp[mm][nn]) + bi;
                if (n < 256) g_q [(size_t)(blk + m) * 256 + n]         = v;
                else         g_kv[(size_t)(blk + m) * 512 + (n - 256)] = v;
            }
        }
    }
}

// ---------------------------------------------------------------------------
// Pass 2: attention, 2 query blocks per CTA, 2 queries per thread, f32x2 math.
// 128 threads: tid = blk*64 + h*8 + qp  (queries 2qp, 2qp+1).
// Static smem pool[10240]: [kvbuf 16x512 = 8192][pce 2048]; obuf (32x260) reuses.
// ---------------------------------------------------------------------------
__global__ __launch_bounds__(128) void attn_kernel(
    const float* __restrict__ w_out, const float* __restrict__ b_out,
    const float* __restrict__ pce,   float* __restrict__ out)
{
    __shared__ float pool[10240];
    float* kvbuf = pool;
    float* pcesm = pool + 8192;

    const int bx  = blockIdx.x;
    const int b   = bx >> 11;
    const int P   = (bx >> 5) & 63;
    const int R0  = (bx & 31) << 1;
    const int tid = threadIdx.x;
    const int blk = tid >> 6;
    const int h   = (tid >> 3) & 7;
    const int qp  = tid & 7;
    const int q0  = qp * 2;
    const int iq  = q0 >> 2, jq = q0 & 3;

    const float LOG2E = 1.4426950408889634f;
    for (int i = tid; i < 2048; i += 128) pcesm[i] = pce[i] * LOG2E;

    // 2 query rows, packed as 16x f32x2 each, pre-scaled by (1/sqrt(DH))*log2(e)
    const float SC = 0.17677669529663687f * LOG2E;
    ull qa[16], qb[16];
    {
        const float* qbase = g_q + (size_t)(((b * 64 + P) * 64 + (R0 + blk)) * 16) * 256 + h * 32;
        const float4* p0 = (const float4*)(qbase + q0 * 256);
        const float4* p1 = (const float4*)(qbase + (q0 + 1) * 256);
        #pragma unroll
        for (int d4 = 0; d4 < 8; d4++) {
            float4 v = p0[d4];
            qa[d4*2+0] = pk(v.x * SC, v.y * SC);
            qa[d4*2+1] = pk(v.z * SC, v.w * SC);
            float4 w = p1[d4];
            qb[d4*2+0] = pk(w.x * SC, w.y * SC);
            qb[d4*2+1] = pk(w.z * SC, w.w * SC);
        }
    }

    ull acc0[16], acc1[16];     // packed d-pair accumulators
    #pragma unroll
    for (int d = 0; d < 16; d++) { acc0[d] = 0ULL; acc1[d] = 0ULL; }
    float m0 = -1e30f, m1 = -1e30f, l0 = 0.f, l1 = 0.f;

    // kv tile list: rows R0-1..R0+2, cols P-1..P+1 (boundary skip == -inf mask)
    int tP[12], tR[12], tC[12];
    int nt = 0;
    for (int rr = 0; rr < 4; rr++) {
        int Rp = R0 - 1 + rr;
        if (Rp < 0 || Rp > 63) continue;
        for (int cc = 0; cc < 3; cc++) {
            int Pp = P - 1 + cc;
            if (Pp < 0 || Pp > 63) continue;
            tP[nt] = Pp; tR[nt] = Rp; tC[nt] = rr * 4 + cc; nt++;
        }
    }

    for (int t = 0; t < nt; t++) {
        __syncthreads();   // previous tile consumed (and pcesm on first iter)
        {
            const float4* src = (const float4*)(g_kv + (size_t)((b * 64 + tP[t]) * 64 + tR[t]) * 16 * 512);
            float4* dst = (float4*)kvbuf;
            #pragma unroll
            for (int ii = 0; ii < 16; ii++) {
                int idx = tid + ii * 128;
                dst[idx] = src[idx];
            }
        }
        __syncthreads();

        const int rr = tC[t] >> 2, cc = tC[t] & 3;
        const bool act = blk ? (rr >= 1) : (rr <= 2);
        if (act) {
            const int dr = rr - blk, dp = cc;

            float s0[16], s1[16];
            #pragma unroll
            for (int kp = 0; kp < 16; kp++) {
                const float* kr = kvbuf + kp * 512 + h * 32;
                ull d0 = 0ULL, d1 = 0ULL;
                #pragma unroll
                for (int dd = 0; dd < 8; dd++) {
                    float4 kk = *(const float4*)(kr + dd * 4);
                    ull k01 = pk(kk.x, kk.y), k23 = pk(kk.z, kk.w);
                    d0 = fma2(qa[dd*2+0], k01, d0);
                    d0 = fma2(qa[dd*2+1], k23, d0);
                    d1 = fma2(qb[dd*2+0], k01, d1);
                    d1 = fma2(qb[dd*2+1], k23, d1);
                }
                int ik = kp >> 2, jk = kp & 3;
                int nu  = dp * 4 + ik + 4 - iq;
                int ntt = dr * 4 + jk + 4 - jq;
                int bidx = h * 256 + nu * 16 + ntt;
                s0[kp] = hsum2(d0) - pcesm[bidx];
                s1[kp] = hsum2(d1) - pcesm[bidx - 1];
            }

            float mb0 = s0[0], mb1 = s1[0];
            #pragma unroll
            for (int kp = 1; kp < 16; kp++) { mb0 = fmaxf(mb0, s0[kp]); mb1 = fmaxf(mb1, s1[kp]); }
            float nm0 = fmaxf(m0, mb0), nm1 = fmaxf(m1, mb1);
            float f0 = ex2f(m0 - nm0), f1 = ex2f(m1 - nm1);
            m0 = nm0; m1 = nm1;
            l0 *= f0;  l1 *= f1;
            ull f0p = pk(f0, f0), f1p = pk(f1, f1);
            #pragma unroll
            for (int d = 0; d < 16; d++) { acc0[d] = mul2(acc0[d], f0p); acc1[d] = mul2(acc1[d], f1p); }

            float sp0 = 0.f, sp1 = 0.f;
            #pragma unroll
            for (int kp = 0; kp < 16; kp++) {
                float p0 = ex2f(s0[kp] - m0);
                float p1 = ex2f(s1[kp] - m1);
                sp0 += p0; sp1 += p1;
                ull pp0 = pk(p0, p0), pp1 = pk(p1, p1);
                const float* vr = kvbuf + kp * 512 + 256 + h * 32;
                #pragma unroll
                for (int dd = 0; dd < 8; dd++) {
                    float4 vv = *(const float4*)(vr + dd * 4);
                    ull v01 = pk(vv.x, vv.y), v23 = pk(vv.z, vv.w);
                    acc0[dd*2+0] = fma2(pp0, v01, acc0[dd*2+0]);
                    acc0[dd*2+1] = fma2(pp0, v23, acc0[dd*2+1]);
                    acc1[dd*2+0] = fma2(pp1, v01, acc1[dd*2+0]);
                    acc1[dd*2+1] = fma2(pp1, v23, acc1[dd*2+1]);
                }
            }
            l0 += sp0; l1 += sp1;
        }
    }

    // Normalize + stage attention output: obuf[pix][k], pix = blk*16 + q, pad 260
    __syncthreads();                    // all kv reads done; obuf aliases kvbuf/pcesm
    float* obuf = pool;
    {
        ull i0 = pk(1.0f / l0, 1.0f / l0), i1 = pk(1.0f / l1, 1.0f / l1);
        float4* r0 = (float4*)(obuf + (blk * 16 + q0)     * 260 + h * 32);
        float4* r1 = (float4*)(obuf + (blk * 16 + q0 + 1) * 260 + h * 32);
        #pragma unroll
        for (int d4 = 0; d4 < 8; d4++) {
            float4 v, w;
            ull a01 = mul2(acc0[d4*2+0], i0), a23 = mul2(acc0[d4*2+1], i0);
            upk(a01, v.x, v.y); upk(a23, v.z, v.w);
            r0[d4] = v;
            ull b01 = mul2(acc1[d4*2+0], i1), b23 = mul2(acc1[d4*2+1], i1);
            upk(b01, w.x, w.y); upk(b23, w.z, w.w);
            r1[d4] = w;
        }
    }
    __syncthreads();

    // Fused output projection: out32x128 = obuf(32x256) @ w_out.T + b_out
    // thread = (j 4, cg 32); packed over k-dim pairs.
    const int j  = tid & 3;
    const int cg = tid >> 2;            // 0..31
    ull accO[2][4][4];
    #pragma unroll
    for (int eb = 0; eb < 2; eb++)
        #pragma unroll
        for (int ci = 0; ci < 4; ci++)
            #pragma unroll
            for (int i = 0; i < 4; i++) accO[eb][ci][i] = 0ULL;

    #pragma unroll 4
    for (int k4 = 0; k4 < 64; k4++) {
        ull o01[2][4], o23[2][4];
        #pragma unroll
        for (int eb = 0; eb < 2; eb++)
            #pragma unroll
            for (int i = 0; i < 4; i++) {
                float4 o = *(const float4*)(obuf + (eb * 16 + i * 4 + j) * 260 + k4 * 4);
                o01[eb][i] = pk(o.x, o.y); o23[eb][i] = pk(o.z, o.w);
            }
        #pragma unroll
        for (int ci = 0; ci < 4; ci++) {
            float4 w4 = __ldg((const float4*)(w_out + (cg * 4 + ci) * 256 + k4 * 4));
            ull w01 = pk(w4.x, w4.y), w23 = pk(w4.z, w4.w);
            #pragma unroll
            for (int eb = 0; eb < 2; eb++)
                #pragma unroll
                for (int i = 0; i < 4; i++) {
                    accO[eb][ci][i] = fma2(w01, o01[eb][i], accO[eb][ci][i]);
                    accO[eb][ci][i] = fma2(w23, o23[eb][i], accO[eb][ci][i]);
                }
        }
    }

    #pragma unroll
    for (int eb = 0; eb < 2; eb++) {
        const int hh = (R0 + eb) * 4 + j;
        #pragma unroll
        for (int ci = 0; ci < 4; ci++) {
            int c = cg * 4 + ci;
            float bo = __ldg(b_out + c);
            float4 r;
            r.x = hsum2(accO[eb][ci][0]) + bo; r.y = hsum2(accO[eb][ci][1]) + bo;
            r.z = hsum2(accO[eb][ci][2]) + bo; r.w = hsum2(accO[eb][ci][3]) + bo;
            *(float4*)(out + ((size_t)(b * 128 + c) * 256 + hh) * 256 + P * 4) = r;
        }
    }
}

// ---------------------------------------------------------------------------
extern "C" void kernel_launch(void* const* d_in, const int* in_sizes, int n_in,
                              void* d_out, int out_size)
{
    const float* x     = (const float*)d_in[0];
    const float* w_in  = (const float*)d_in[1];
    const float* b_in  = (const float*)d_in[2];
    const float* w_out = (const float*)d_in[3];
    const float* b_out = (const float*)d_in[4];
    const float* pce   = (const float*)d_in[5];
    float* out = (float*)d_out;

    proj_kernel<<<2048, 256>>>(x, w_in, b_in);
    attn_kernel<<<4096, 128>>>(w_out, b_out, pce, out);
}